// round 1
// baseline (speedup 1.0000x reference)
#include <cuda_runtime.h>
#include <math.h>

// Problem constants
#define Pw    7
#define PP    49
#define HEADS 8
#define DH    32
#define INNER 256          // HEADS*DH
#define Cc    128
#define Bb    32
#define HW    56
#define WINS  2048         // Bb * 8 * 8
#define MROWS (WINS*PP)    // 100352

// Scratch (static __device__ — no allocations allowed)
static __device__ float g_qkv [(size_t)MROWS * 3 * INNER]; // 100352 x 768
static __device__ float g_omid[(size_t)MROWS * INNER];     // 100352 x 256
static __device__ float g_attn_dump[(size_t)WINS * HEADS * PP * PP];
static __device__ float g_o_dump  [(size_t)Bb * Cc * HW * HW];

// ---------------------------------------------------------------------------
// Kernel 1: fused gather (roll -3,-3 + window partition) + QKV GEMM
// qkv[row, oc] = sum_c xw[row, c] * w_qkv[oc, c]
// M = 100352, N = 768, K = 128.  64x64x16 tiling, 256 threads, 4x4 microtile.
// ---------------------------------------------------------------------------
__global__ void qkv_gemm_kernel(const float* __restrict__ x,
                                const float* __restrict__ w_qkv)
{
    __shared__ float As[16][68];
    __shared__ float Bs[16][68];

    const int tid = threadIdx.x;
    const int bm = blockIdx.y * 64;
    const int bn = blockIdx.x * 64;

    // --- A gather base: this thread loads column m = tid%64 of the A tile ---
    const int mA  = tid & 63;
    const int row = bm + mA;
    const int win = row / PP;
    const int t   = row - win * PP;
    const int b   = win >> 6;
    const int wl  = win & 63;
    const int i1  = wl >> 3, i2 = wl & 7;
    const int xx  = t / Pw,  yy = t - (t / Pw) * Pw;
    int h = i1 * Pw + xx + 3; if (h >= HW) h -= HW;   // roll(-3) gather
    int w = i2 * Pw + yy + 3; if (w >= HW) w -= HW;
    const float* xbase = x + (size_t)b * Cc * HW * HW + (size_t)h * HW + w;
    const int kA0 = tid >> 6;          // 0..3, loads k = kA0 + 4j

    const int kB  = tid & 15;
    const int nB0 = tid >> 4;          // 0..15, loads n = nB0 + 16j

    const int tx = tid & 15, ty = tid >> 4;
    float acc[4][4] = {};

    for (int k0 = 0; k0 < Cc; k0 += 16) {
        #pragma unroll
        for (int j = 0; j < 4; j++) {
            int k = kA0 + 4 * j;
            As[k][mA] = xbase[(size_t)(k0 + k) * (HW * HW)];
        }
        #pragma unroll
        for (int j = 0; j < 4; j++) {
            int n = nB0 + 16 * j;
            Bs[kB][n] = w_qkv[(size_t)(bn + n) * Cc + k0 + kB];
        }
        __syncthreads();
        #pragma unroll
        for (int kk = 0; kk < 16; kk++) {
            float4 a  = *(const float4*)&As[kk][ty * 4];
            float4 bq = *(const float4*)&Bs[kk][tx * 4];
            float av[4] = {a.x, a.y, a.z, a.w};
            float bv[4] = {bq.x, bq.y, bq.z, bq.w};
            #pragma unroll
            for (int i = 0; i < 4; i++)
                #pragma unroll
                for (int j = 0; j < 4; j++)
                    acc[i][j] = fmaf(av[i], bv[j], acc[i][j]);
        }
        __syncthreads();
    }

    #pragma unroll
    for (int i = 0; i < 4; i++) {
        int r = bm + ty * 4 + i;
        float4 v4 = make_float4(acc[i][0], acc[i][1], acc[i][2], acc[i][3]);
        *(float4*)&g_qkv[(size_t)r * 768 + bn + tx * 4] = v4;
    }
}

// ---------------------------------------------------------------------------
// Kernel 2: per-(window, head) attention. 16384 blocks x 128 threads.
// ---------------------------------------------------------------------------
__global__ void attn_kernel(const float* __restrict__ pos,
                            float* __restrict__ attn_out)
{
    const int blk  = blockIdx.x;       // win*8 + head
    const int win  = blk >> 3;
    const int head = blk & 7;
    const int wl   = win & 63;
    const bool ul = (wl >= 56);                 // m1: x-group mismatch mask
    const bool lr = (wl == 55) || (wl == 63);   // m2: y-group mismatch mask

    __shared__ float q[PP][33], k[PP][33], v[PP][33];
    __shared__ float s[PP][PP];

    const int tid = threadIdx.x;
    const float* qb = g_qkv + (size_t)win * PP * 768;

    for (int idx = tid; idx < PP * DH; idx += 128) {
        int tt = idx >> 5, d = idx & 31;
        q[tt][d] = qb[tt * 768 +       head * 32 + d];
        k[tt][d] = qb[tt * 768 + 256 + head * 32 + d];
        v[tt][d] = qb[tt * 768 + 512 + head * 32 + d];
    }
    __syncthreads();

    const float scale = 0.1767766952966369f;  // 32^-0.5
    for (int idx = tid; idx < PP * PP; idx += 128) {
        int i = idx / PP, j = idx - i * PP;
        float sum = 0.f;
        #pragma unroll
        for (int d = 0; d < DH; d++) sum = fmaf(q[i][d], k[j][d], sum);
        int xi = i / Pw, yi = i - xi * Pw;
        int xj = j / Pw, yj = j - xj * Pw;
        float val = sum * scale + pos[(xj - xi + 6) * 13 + (yj - yi + 6)];
        if (ul && ((i >= 28) != (j >= 28))) val = -1e30f;
        if (lr && ((yi >= 4) != (yj >= 4))) val = -1e30f;
        s[i][j] = val;
    }
    __syncthreads();

    if (tid < PP) {
        float mx = -1e30f;
        for (int j = 0; j < PP; j++) mx = fmaxf(mx, s[tid][j]);
        float sum = 0.f;
        for (int j = 0; j < PP; j++) { float e = __expf(s[tid][j] - mx); s[tid][j] = e; sum += e; }
        float inv = 1.0f / sum;
        for (int j = 0; j < PP; j++) s[tid][j] *= inv;
    }
    __syncthreads();

    float* aout = attn_out + (size_t)blk * PP * PP;
    for (int idx = tid; idx < PP * PP; idx += 128) {
        int i = idx / PP;
        aout[idx] = s[i][idx - i * PP];
    }

    float* ob = g_omid + (size_t)win * PP * INNER + head * 32;
    for (int idx = tid; idx < PP * DH; idx += 128) {
        int i = idx >> 5, d = idx & 31;
        float sum = 0.f;
        #pragma unroll
        for (int j = 0; j < PP; j++) sum = fmaf(s[i][j], v[j][d], sum);
        ob[(size_t)i * INNER + d] = sum;
    }
}

// ---------------------------------------------------------------------------
// Kernel 3: out = o_mid @ w_out^T + b_out, scattered back with roll(+3,+3)
// M = 100352, N = 128, K = 256.
// ---------------------------------------------------------------------------
__global__ void out_gemm_kernel(const float* __restrict__ w_out,
                                const float* __restrict__ b_out,
                                float* __restrict__ out)
{
    __shared__ float As[16][68];
    __shared__ float Bs[16][68];

    const int tid = threadIdx.x;
    const int bm = blockIdx.y * 64;
    const int bn = blockIdx.x * 64;

    const int kL  = tid & 15;
    const int mL0 = tid >> 4;
    const int tx = tid & 15, ty = tid >> 4;
    float acc[4][4] = {};

    for (int k0 = 0; k0 < INNER; k0 += 16) {
        #pragma unroll
        for (int j = 0; j < 4; j++) {
            int m = mL0 + 16 * j;
            As[kL][m] = g_omid[(size_t)(bm + m) * INNER + k0 + kL];
            Bs[kL][m] = w_out [(size_t)(bn + m) * INNER + k0 + kL];
        }
        __syncthreads();
        #pragma unroll
        for (int kk = 0; kk < 16; kk++) {
            float4 a  = *(const float4*)&As[kk][ty * 4];
            float4 bq = *(const float4*)&Bs[kk][tx * 4];
            float av[4] = {a.x, a.y, a.z, a.w};
            float bv[4] = {bq.x, bq.y, bq.z, bq.w};
            #pragma unroll
            for (int i = 0; i < 4; i++)
                #pragma unroll
                for (int j = 0; j < 4; j++)
                    acc[i][j] = fmaf(av[i], bv[j], acc[i][j]);
        }
        __syncthreads();
    }

    #pragma unroll
    for (int i = 0; i < 4; i++) {
        int row = bm + ty * 4 + i;
        int win = row / PP;
        int t   = row - win * PP;
        int b   = win >> 6;
        int wl  = win & 63;
        int i1  = wl >> 3, i2 = wl & 7;
        int xx  = t / Pw,  yy = t - (t / Pw) * Pw;
        int h = i1 * Pw + xx + 3; if (h >= HW) h -= HW;   // roll(+3) scatter == same index map
        int w = i2 * Pw + yy + 3; if (w >= HW) w -= HW;
        size_t base = (size_t)b * Cc * HW * HW + (size_t)h * HW + w;
        #pragma unroll
        for (int j = 0; j < 4; j++) {
            int n = bn + tx * 4 + j;
            out[base + (size_t)n * (HW * HW)] = acc[i][j] + b_out[n];
        }
    }
}

// ---------------------------------------------------------------------------
extern "C" void kernel_launch(void* const* d_in, const int* in_sizes, int n_in,
                              void* d_out, int out_size)
{
    const float* x      = (const float*)d_in[0];
    const float* w_qkv  = (const float*)d_in[1];
    const float* w_out  = (const float*)d_in[2];
    const float* b_out  = (const float*)d_in[3];
    const float* pos    = (const float*)d_in[4];

    const long long O_ELEMS = (long long)Bb * Cc * HW * HW;          // 12845056
    const long long A_ELEMS = (long long)WINS * HEADS * PP * PP;     // 39337984

    float* out = (float*)d_out;
    float* o_ptr;
    float* attn_ptr;

    if ((long long)out_size >= O_ELEMS + A_ELEMS) {
        o_ptr    = out;
        attn_ptr = out + O_ELEMS;
    } else if ((long long)out_size == A_ELEMS) {
        // output is attn only
        attn_ptr = out;
        cudaGetSymbolAddress((void**)&o_ptr, g_o_dump);
    } else {
        // output is o only
        o_ptr = out;
        cudaGetSymbolAddress((void**)&attn_ptr, g_attn_dump);
    }

    qkv_gemm_kernel<<<dim3(768 / 64, MROWS / 64), 256>>>(x, w_qkv);
    attn_kernel<<<WINS * HEADS, 128>>>(pos, attn_ptr);
    out_gemm_kernel<<<dim3(Cc / 64, MROWS / 64), 256>>>(w_out, b_out, o_ptr);
}

// round 2
// speedup vs baseline: 2.0139x; 2.0139x over previous
#include <cuda_runtime.h>
#include <math.h>

#define Pw    7
#define PP    49
#define HEADS 8
#define DH    32
#define INNER 256
#define Cc    128
#define Bb    32
#define HW    56
#define WINS  2048
#define MROWS (WINS*PP)    // 100352

static __device__ float g_qkv [(size_t)MROWS * 3 * INNER];
static __device__ float g_omid[(size_t)MROWS * INNER];
static __device__ float g_wqkv_t[768 * 128];   // [k][n] = w_qkv[n][k]
static __device__ float g_wout_t[256 * 128];   // [k][n] = w_out[n][k]
static __device__ float g_attn_dump[(size_t)WINS * HEADS * PP * PP];
static __device__ float g_o_dump  [(size_t)Bb * Cc * HW * HW];

__device__ __forceinline__ unsigned f2tf32(float f) {
    unsigned u; asm("cvt.rna.tf32.f32 %0, %1;" : "=r"(u) : "f"(f)); return u;
}
__device__ __forceinline__ void mma_tf32(float c[4],
    unsigned a0, unsigned a1, unsigned a2, unsigned a3,
    unsigned b0, unsigned b1)
{
    asm volatile(
        "mma.sync.aligned.m16n8k8.row.col.f32.tf32.tf32.f32 "
        "{%0,%1,%2,%3}, {%4,%5,%6,%7}, {%8,%9}, {%0,%1,%2,%3};"
        : "+f"(c[0]), "+f"(c[1]), "+f"(c[2]), "+f"(c[3])
        : "r"(a0), "r"(a1), "r"(a2), "r"(a3), "r"(b0), "r"(b1));
}

// ---------------------------------------------------------------------------
// Kernel 0: transpose weights once (tiny)
// ---------------------------------------------------------------------------
__global__ void transpose_w(const float* __restrict__ wq, const float* __restrict__ wo)
{
    int idx = blockIdx.x * 256 + threadIdx.x;
    if (idx < 768 * 128) {
        int k = idx / 768, n = idx - k * 768;
        g_wqkv_t[idx] = wq[n * 128 + k];
    }
    int i2 = idx - 768 * 128;
    if (i2 >= 0 && i2 < 256 * 128) {
        int k = i2 / 128, n = i2 - k * 128;
        g_wout_t[i2] = wo[n * 256 + k];
    }
}

// ---------------------------------------------------------------------------
// Kernel 1: fused gather + QKV GEMM, tf32 tensor cores.
// M=100352, N=768, K=128. Block tile 128x128, 8 warps (2x4), warp tile 64x32.
// ---------------------------------------------------------------------------
__global__ void qkv_gemm_tc(const float* __restrict__ x)
{
    __shared__ unsigned As[16][132];
    __shared__ unsigned Bs[16][132];

    const int tid  = threadIdx.x;
    const int bm   = blockIdx.y * 128;
    const int bn   = blockIdx.x * 128;
    const int lane = tid & 31, wid = tid >> 5;
    const int wm   = (wid & 1) * 64, wn = (wid >> 1) * 32;

    // A gather mapping (roll -3,-3 + window partition), verified in R1
    const int mA = tid & 127, kA = (tid >> 7) * 8;
    {
        // nothing
    }
    const int row = bm + mA;
    const int win = row / PP;
    const int t   = row - win * PP;
    const int b   = win >> 6;
    const int wl  = win & 63;
    const int i1  = wl >> 3, i2 = wl & 7;
    const int xx  = t / Pw,  yy = t - (t / Pw) * Pw;
    int h = i1 * Pw + xx + 3; if (h >= HW) h -= HW;
    int w = i2 * Pw + yy + 3; if (w >= HW) w -= HW;
    const float* xbase = x + (size_t)b * Cc * HW * HW + (size_t)h * HW + w;

    const int kB = tid >> 4, n8 = (tid & 15) * 8;
    const float* wb = g_wqkv_t + bn + n8;

    float acc[4][4][4];
    #pragma unroll
    for (int i = 0; i < 4; i++)
        #pragma unroll
        for (int j = 0; j < 4; j++)
            #pragma unroll
            for (int c = 0; c < 4; c++) acc[i][j][c] = 0.f;

    for (int k0 = 0; k0 < Cc; k0 += 16) {
        #pragma unroll
        for (int j = 0; j < 8; j++)
            As[kA + j][mA] = f2tf32(xbase[(size_t)(k0 + kA + j) * (HW * HW)]);
        {
            float4 w0 = *(const float4*)(wb + (size_t)(k0 + kB) * 768);
            float4 w1 = *(const float4*)(wb + (size_t)(k0 + kB) * 768 + 4);
            Bs[kB][n8 + 0] = f2tf32(w0.x); Bs[kB][n8 + 1] = f2tf32(w0.y);
            Bs[kB][n8 + 2] = f2tf32(w0.z); Bs[kB][n8 + 3] = f2tf32(w0.w);
            Bs[kB][n8 + 4] = f2tf32(w1.x); Bs[kB][n8 + 5] = f2tf32(w1.y);
            Bs[kB][n8 + 6] = f2tf32(w1.z); Bs[kB][n8 + 7] = f2tf32(w1.w);
        }
        __syncthreads();
        #pragma unroll
        for (int k8 = 0; k8 < 16; k8 += 8) {
            unsigned af[4][4], bf[4][2];
            const int kk = k8 + (lane & 3);
            #pragma unroll
            for (int mt = 0; mt < 4; mt++) {
                int r = wm + mt * 16 + (lane >> 2);
                af[mt][0] = As[kk][r];     af[mt][1] = As[kk][r + 8];
                af[mt][2] = As[kk + 4][r]; af[mt][3] = As[kk + 4][r + 8];
            }
            #pragma unroll
            for (int nt = 0; nt < 4; nt++) {
                int c = wn + nt * 8 + (lane >> 2);
                bf[nt][0] = Bs[kk][c]; bf[nt][1] = Bs[kk + 4][c];
            }
            #pragma unroll
            for (int mt = 0; mt < 4; mt++)
                #pragma unroll
                for (int nt = 0; nt < 4; nt++)
                    mma_tf32(acc[mt][nt], af[mt][0], af[mt][1], af[mt][2], af[mt][3],
                             bf[nt][0], bf[nt][1]);
        }
        __syncthreads();
    }

    #pragma unroll
    for (int mt = 0; mt < 4; mt++) {
        int r0 = bm + wm + mt * 16 + (lane >> 2);
        #pragma unroll
        for (int nt = 0; nt < 4; nt++) {
            int c = bn + wn + nt * 8 + (lane & 3) * 2;
            *(float2*)&g_qkv[(size_t)r0 * 768 + c] =
                make_float2(acc[mt][nt][0], acc[mt][nt][1]);
            *(float2*)&g_qkv[(size_t)(r0 + 8) * 768 + c] =
                make_float2(acc[mt][nt][2], acc[mt][nt][3]);
        }
    }
}

// ---------------------------------------------------------------------------
// Kernel 2: attention, thread-per-row, q in registers, broadcast K/V reads.
// 16384 blocks x 64 threads.
// ---------------------------------------------------------------------------
__global__ void attn_kernel(const float* __restrict__ pos,
                            float* __restrict__ attn_out)
{
    const int blk  = blockIdx.x;
    const int win  = blk >> 3;
    const int head = blk & 7;
    const int wl   = win & 63;
    const bool ul = (wl >= 56);
    const bool lr = (wl == 55) || (wl == 63);

    __shared__ float ksm[PP][32];
    __shared__ float vsm[PP][32];
    __shared__ float ssm[PP][50];
    __shared__ float psm[169];

    const int tid = threadIdx.x;
    const float* qb = g_qkv + (size_t)win * PP * 768;

    for (int idx = tid; idx < PP * DH; idx += 64) {
        int tt = idx >> 5, d = idx & 31;
        ksm[tt][d] = qb[tt * 768 + 256 + head * 32 + d];
        vsm[tt][d] = qb[tt * 768 + 512 + head * 32 + d];
    }
    for (int idx = tid; idx < 169; idx += 64) psm[idx] = pos[idx];

    float4 q4[8];
    const int i = tid;
    if (i < PP) {
        const float4* qp = (const float4*)(qb + i * 768 + head * 32);
        #pragma unroll
        for (int d4 = 0; d4 < 8; d4++) q4[d4] = qp[d4];
    }
    __syncthreads();

    const float scale = 0.1767766952966369f;  // 32^-0.5

    if (i < PP) {
        const int xi = i / Pw, yi = i - xi * Pw;
        int xj = 0, yj = 0;
        float mx = -1e30f;
        for (int j = 0; j < PP; j++) {
            const float4* krow = (const float4*)ksm[j];
            float s0 = 0.f, s1 = 0.f;
            #pragma unroll
            for (int d4 = 0; d4 < 8; d4 += 2) {
                float4 ka = krow[d4], kb = krow[d4 + 1];
                s0 = fmaf(q4[d4].x, ka.x, s0);   s0 = fmaf(q4[d4].y, ka.y, s0);
                s0 = fmaf(q4[d4].z, ka.z, s0);   s0 = fmaf(q4[d4].w, ka.w, s0);
                s1 = fmaf(q4[d4+1].x, kb.x, s1); s1 = fmaf(q4[d4+1].y, kb.y, s1);
                s1 = fmaf(q4[d4+1].z, kb.z, s1); s1 = fmaf(q4[d4+1].w, kb.w, s1);
            }
            float val = (s0 + s1) * scale + psm[(xj - xi + 6) * 13 + (yj - yi + 6)];
            if (ul && ((i >= 28) != (j >= 28))) val = -1e30f;
            if (lr && ((yi >= 4) != (yj >= 4))) val = -1e30f;
            ssm[i][j] = val;
            mx = fmaxf(mx, val);
            if (++yj == Pw) { yj = 0; xj++; }
        }
        // softmax on own row
        float sum = 0.f;
        for (int j = 0; j < PP; j++) {
            float e = __expf(ssm[i][j] - mx);
            ssm[i][j] = e;
            sum += e;
        }
        float inv = 1.0f / sum;
        for (int j = 0; j < PP; j++) ssm[i][j] *= inv;
    }
    __syncthreads();

    // coalesced attn write
    float* aout = attn_out + (size_t)blk * PP * PP;
    for (int idx = tid; idx < PP * PP; idx += 64) {
        int r = idx / PP;
        aout[idx] = ssm[r][idx - r * PP];
    }

    // o = p @ v, per-row
    if (i < PP) {
        float4 o4[8];
        #pragma unroll
        for (int d4 = 0; d4 < 8; d4++) o4[d4] = make_float4(0.f, 0.f, 0.f, 0.f);
        for (int j = 0; j < PP; j++) {
            float p = ssm[i][j];
            const float4* vrow = (const float4*)vsm[j];
            #pragma unroll
            for (int d4 = 0; d4 < 8; d4++) {
                float4 vv = vrow[d4];
                o4[d4].x = fmaf(p, vv.x, o4[d4].x);
                o4[d4].y = fmaf(p, vv.y, o4[d4].y);
                o4[d4].z = fmaf(p, vv.z, o4[d4].z);
                o4[d4].w = fmaf(p, vv.w, o4[d4].w);
            }
        }
        float4* ob = (float4*)(g_omid + ((size_t)win * PP + i) * INNER + head * 32);
        #pragma unroll
        for (int d4 = 0; d4 < 8; d4++) ob[d4] = o4[d4];
    }
}

// ---------------------------------------------------------------------------
// Kernel 3: out GEMM tf32 + bias + roll-back scatter.
// M=100352, N=128, K=256. Block tile 128x128 (full N), 8 warps.
// ---------------------------------------------------------------------------
__global__ void out_gemm_tc(const float* __restrict__ b_out,
                            float* __restrict__ out)
{
    __shared__ unsigned As[16][132];
    __shared__ unsigned Bs[16][132];

    const int tid  = threadIdx.x;
    const int bm   = blockIdx.y * 128;
    const int lane = tid & 31, wid = tid >> 5;
    const int wm   = (wid & 1) * 64, wn = (wid >> 1) * 32;

    const int mL = tid >> 1, kq = (tid & 1) * 8;
    const int kB = tid >> 4, n8 = (tid & 15) * 8;

    float acc[4][4][4];
    #pragma unroll
    for (int i = 0; i < 4; i++)
        #pragma unroll
        for (int j = 0; j < 4; j++)
            #pragma unroll
            for (int c = 0; c < 4; c++) acc[i][j][c] = 0.f;

    for (int k0 = 0; k0 < INNER; k0 += 16) {
        {
            const float4* ap = (const float4*)(g_omid + (size_t)(bm + mL) * INNER + k0 + kq);
            float4 a0 = ap[0], a1 = ap[1];
            As[kq + 0][mL] = f2tf32(a0.x); As[kq + 1][mL] = f2tf32(a0.y);
            As[kq + 2][mL] = f2tf32(a0.z); As[kq + 3][mL] = f2tf32(a0.w);
            As[kq + 4][mL] = f2tf32(a1.x); As[kq + 5][mL] = f2tf32(a1.y);
            As[kq + 6][mL] = f2tf32(a1.z); As[kq + 7][mL] = f2tf32(a1.w);
        }
        {
            const float4* bp = (const float4*)(g_wout_t + (size_t)(k0 + kB) * 128 + n8);
            float4 w0 = bp[0], w1 = bp[1];
            Bs[kB][n8 + 0] = f2tf32(w0.x); Bs[kB][n8 + 1] = f2tf32(w0.y);
            Bs[kB][n8 + 2] = f2tf32(w0.z); Bs[kB][n8 + 3] = f2tf32(w0.w);
            Bs[kB][n8 + 4] = f2tf32(w1.x); Bs[kB][n8 + 5] = f2tf32(w1.y);
            Bs[kB][n8 + 6] = f2tf32(w1.z); Bs[kB][n8 + 7] = f2tf32(w1.w);
        }
        __syncthreads();
        #pragma unroll
        for (int k8 = 0; k8 < 16; k8 += 8) {
            unsigned af[4][4], bf[4][2];
            const int kk = k8 + (lane & 3);
            #pragma unroll
            for (int mt = 0; mt < 4; mt++) {
                int r = wm + mt * 16 + (lane >> 2);
                af[mt][0] = As[kk][r];     af[mt][1] = As[kk][r + 8];
                af[mt][2] = As[kk + 4][r]; af[mt][3] = As[kk + 4][r + 8];
            }
            #pragma unroll
            for (int nt = 0; nt < 4; nt++) {
                int c = wn + nt * 8 + (lane >> 2);
                bf[nt][0] = Bs[kk][c]; bf[nt][1] = Bs[kk + 4][c];
            }
            #pragma unroll
            for (int mt = 0; mt < 4; mt++)
                #pragma unroll
                for (int nt = 0; nt < 4; nt++)
                    mma_tf32(acc[mt][nt], af[mt][0], af[mt][1], af[mt][2], af[mt][3],
                             bf[nt][0], bf[nt][1]);
        }
        __syncthreads();
    }

    // epilogue: bias + scatter with roll(+3,+3)
    #pragma unroll
    for (int mt = 0; mt < 4; mt++) {
        #pragma unroll
        for (int half = 0; half < 2; half++) {
            int r = bm + wm + mt * 16 + (lane >> 2) + half * 8;
            int win = r / PP;
            int t   = r - win * PP;
            int b   = win >> 6;
            int wl  = win & 63;
            int i1  = wl >> 3, i2 = wl & 7;
            int xx  = t / Pw,  yy = t - (t / Pw) * Pw;
            int h = i1 * Pw + xx + 3; if (h >= HW) h -= HW;
            int w = i2 * Pw + yy + 3; if (w >= HW) w -= HW;
            size_t base = (size_t)b * Cc * HW * HW + (size_t)h * HW + w;
            #pragma unroll
            for (int nt = 0; nt < 4; nt++) {
                int c = wn + nt * 8 + (lane & 3) * 2;
                out[base + (size_t)c * (HW * HW)]       = acc[mt][nt][half * 2 + 0] + b_out[c];
                out[base + (size_t)(c + 1) * (HW * HW)] = acc[mt][nt][half * 2 + 1] + b_out[c + 1];
            }
        }
    }
}

// ---------------------------------------------------------------------------
extern "C" void kernel_launch(void* const* d_in, const int* in_sizes, int n_in,
                              void* d_out, int out_size)
{
    const float* x      = (const float*)d_in[0];
    const float* w_qkv  = (const float*)d_in[1];
    const float* w_out  = (const float*)d_in[2];
    const float* b_out  = (const float*)d_in[3];
    const float* pos    = (const float*)d_in[4];

    const long long O_ELEMS = (long long)Bb * Cc * HW * HW;
    const long long A_ELEMS = (long long)WINS * HEADS * PP * PP;

    float* outp = (float*)d_out;
    float* o_ptr;
    float* attn_ptr;

    if ((long long)out_size >= O_ELEMS + A_ELEMS) {
        o_ptr    = outp;
        attn_ptr = outp + O_ELEMS;
    } else if ((long long)out_size == A_ELEMS) {
        attn_ptr = outp;
        cudaGetSymbolAddress((void**)&o_ptr, g_o_dump);
    } else {
        o_ptr = outp;
        cudaGetSymbolAddress((void**)&attn_ptr, g_attn_dump);
    }

    transpose_w<<<512, 256>>>(w_qkv, w_out);
    qkv_gemm_tc<<<dim3(768 / 128, MROWS / 128), 256>>>(x);
    attn_kernel<<<WINS * HEADS, 64>>>(pos, attn_ptr);
    out_gemm_tc<<<dim3(1, MROWS / 128), 256>>>(b_out, o_ptr);
}

// round 4
// speedup vs baseline: 2.1547x; 1.0699x over previous
#include <cuda_runtime.h>
#include <stdint.h>
#include <math.h>

#define Pw    7
#define PP    49
#define HEADS 8
#define DH    32
#define INNER 256
#define Cc    128
#define Bb    32
#define HW    56
#define WINS  2048
#define MROWS (WINS*PP)    // 100352

static __device__ float g_xw  [(size_t)MROWS * Cc];        // gathered+tf32 activations
static __device__ float g_qkv [(size_t)MROWS * 3 * INNER];
static __device__ float g_omid[(size_t)MROWS * INNER];
static __device__ float g_wqkv_t[768 * 128];   // [k][n], tf32-rounded
static __device__ float g_wout_t[256 * 128];   // [k][n], tf32-rounded
static __device__ float g_attn_dump[(size_t)WINS * HEADS * PP * PP];
static __device__ float g_o_dump  [(size_t)Bb * Cc * HW * HW];

__device__ __forceinline__ unsigned int f2tf32(float f) {
    unsigned int u; asm("cvt.rna.tf32.f32 %0, %1;" : "=r"(u) : "f"(f)); return u;
}
__device__ __forceinline__ float tf32r(float f) { return __uint_as_float(f2tf32(f)); }

__device__ __forceinline__ void mma_tf32(float c[4],
    unsigned int a0, unsigned int a1, unsigned int a2, unsigned int a3,
    unsigned int b0, unsigned int b1)
{
    asm volatile(
        "mma.sync.aligned.m16n8k8.row.col.f32.tf32.tf32.f32 "
        "{%0,%1,%2,%3}, {%4,%5,%6,%7}, {%8,%9}, {%0,%1,%2,%3};"
        : "+f"(c[0]), "+f"(c[1]), "+f"(c[2]), "+f"(c[3])
        : "r"(a0), "r"(a1), "r"(a2), "r"(a3), "r"(b0), "r"(b1));
}

__device__ __forceinline__ void cp16(unsigned int saddr, const void* gaddr) {
    asm volatile("cp.async.cg.shared.global [%0], [%1], 16;" :: "r"(saddr), "l"(gaddr));
}
__device__ __forceinline__ void cp_commit() { asm volatile("cp.async.commit_group;"); }
__device__ __forceinline__ void cp_wait1()  { asm volatile("cp.async.wait_group 1;"); }
__device__ __forceinline__ void cp_wait0()  { asm volatile("cp.async.wait_group 0;"); }

// ---------------------------------------------------------------------------
// Kernel 0: transpose + tf32-round weights (tiny)
// ---------------------------------------------------------------------------
__global__ void transpose_w(const float* __restrict__ wq, const float* __restrict__ wo)
{
    int idx = blockIdx.x * 256 + threadIdx.x;
    if (idx < 768 * 128) {
        int k = idx / 768, n = idx - k * 768;
        g_wqkv_t[idx] = tf32r(wq[n * 128 + k]);
    }
    int i2 = idx - 768 * 128;
    if (i2 >= 0 && i2 < 256 * 128) {
        int k = i2 / 128, n = i2 - k * 128;
        g_wout_t[i2] = tf32r(wo[n * 256 + k]);
    }
}

// ---------------------------------------------------------------------------
// Kernel 1: gather (roll -3,-3 + window partition) -> g_xw, tf32-rounded.
// ---------------------------------------------------------------------------
__global__ void gather_x(const float* __restrict__ x)
{
    __shared__ float sm[128][65];
    const int b  = blockIdx.x / 49;
    const int p0 = (blockIdx.x - b * 49) * 64;
    const int tid = threadIdx.x;

    for (int i = tid; i < 128 * 64; i += 256) {
        int c = i >> 6, p = i & 63;
        sm[c][p] = x[((size_t)b * 128 + c) * 3136 + p0 + p];
    }
    __syncthreads();
    for (int i = tid; i < 64 * 128; i += 256) {
        int p = i >> 7, c = i & 127;
        int pix = p0 + p;
        int h = pix / HW, w = pix - h * HW;
        int hs = h - 3; if (hs < 0) hs += HW;
        int ws = w - 3; if (ws < 0) ws += HW;
        int win = b * 64 + (hs / Pw) * 8 + (ws / Pw);
        int t   = (hs % Pw) * Pw + (ws % Pw);
        g_xw[((size_t)win * PP + t) * Cc + c] = tf32r(sm[c][p]);
    }
}

// ---------------------------------------------------------------------------
// Kernel 2: QKV GEMM, tf32 TC, 2-stage cp.async pipeline.
// M=100352, N=768, K=128. Block 128x128, 8 warps, warp 64x32.
// ---------------------------------------------------------------------------
__global__ void qkv_gemm_tc()
{
    __shared__ float As[2][128][20];
    __shared__ float Bs[2][16][136];

    const int tid  = threadIdx.x;
    const int bm   = blockIdx.y * 128;
    const int bn   = blockIdx.x * 128;
    const int lane = tid & 31, wid = tid >> 5;
    const int wm   = (wid & 1) * 64, wn = (wid >> 1) * 32;

    const int ar = tid & 127, ak = (tid >> 7) * 4;
    const float* agp = g_xw + (size_t)(bm + ar) * Cc + ak;
    const int bk = tid >> 4, bn8 = (tid & 15) * 8;
    const float* bgp = g_wqkv_t + (size_t)bk * 768 + bn + bn8;

    unsigned int sA0 = (unsigned int)__cvta_generic_to_shared(&As[0][ar][ak]);
    unsigned int sA1 = (unsigned int)__cvta_generic_to_shared(&As[1][ar][ak]);
    unsigned int sB0 = (unsigned int)__cvta_generic_to_shared(&Bs[0][bk][bn8]);
    unsigned int sB1 = (unsigned int)__cvta_generic_to_shared(&Bs[1][bk][bn8]);

    float acc[4][4][4];
    #pragma unroll
    for (int i = 0; i < 4; i++)
        #pragma unroll
        for (int j = 0; j < 4; j++)
            #pragma unroll
            for (int c = 0; c < 4; c++) acc[i][j][c] = 0.f;

    cp16(sA0,      agp);
    cp16(sA0 + 32, agp + 8);
    cp16(sB0,      bgp);
    cp16(sB0 + 16, bgp + 4);
    cp_commit();

    #pragma unroll
    for (int ks = 0; ks < 8; ks++) {
        if (ks < 7) {
            const int k0 = (ks + 1) * 16;
            unsigned int dA = ((ks + 1) & 1) ? sA1 : sA0;
            unsigned int dB = ((ks + 1) & 1) ? sB1 : sB0;
            cp16(dA,      agp + k0);
            cp16(dA + 32, agp + k0 + 8);
            cp16(dB,      bgp + (size_t)k0 * 768);
            cp16(dB + 16, bgp + (size_t)k0 * 768 + 4);
            cp_commit();
            cp_wait1();
        } else {
            cp_wait0();
        }
        __syncthreads();
        const int st = ks & 1;
        #pragma unroll
        for (int k8 = 0; k8 < 16; k8 += 8) {
            unsigned int af[4][4], bf[4][2];
            const int kk = k8 + (lane & 3);
            #pragma unroll
            for (int mt = 0; mt < 4; mt++) {
                int r = wm + mt * 16 + (lane >> 2);
                af[mt][0] = __float_as_uint(As[st][r][kk]);
                af[mt][1] = __float_as_uint(As[st][r + 8][kk]);
                af[mt][2] = __float_as_uint(As[st][r][kk + 4]);
                af[mt][3] = __float_as_uint(As[st][r + 8][kk + 4]);
            }
            #pragma unroll
            for (int nt = 0; nt < 4; nt++) {
                int c = wn + nt * 8 + (lane >> 2);
                bf[nt][0] = __float_as_uint(Bs[st][kk][c]);
                bf[nt][1] = __float_as_uint(Bs[st][kk + 4][c]);
            }
            #pragma unroll
            for (int mt = 0; mt < 4; mt++)
                #pragma unroll
                for (int nt = 0; nt < 4; nt++)
                    mma_tf32(acc[mt][nt], af[mt][0], af[mt][1], af[mt][2], af[mt][3],
                             bf[nt][0], bf[nt][1]);
        }
        __syncthreads();
    }

    #pragma unroll
    for (int mt = 0; mt < 4; mt++) {
        int r0 = bm + wm + mt * 16 + (lane >> 2);
        #pragma unroll
        for (int nt = 0; nt < 4; nt++) {
            int c = bn + wn + nt * 8 + (lane & 3) * 2;
            *(float2*)&g_qkv[(size_t)r0 * 768 + c] =
                make_float2(acc[mt][nt][0], acc[mt][nt][1]);
            *(float2*)&g_qkv[(size_t)(r0 + 8) * 768 + c] =
                make_float2(acc[mt][nt][2], acc[mt][nt][3]);
        }
    }
}

// ---------------------------------------------------------------------------
// Kernel 3: attention (per window-head; q in registers, tf32-rounded omid)
// ---------------------------------------------------------------------------
__global__ void attn_kernel(const float* __restrict__ pos,
                            float* __restrict__ attn_out)
{
    const int blk  = blockIdx.x;
    const int win  = blk >> 3;
    const int head = blk & 7;
    const int wl   = win & 63;
    const bool ul = (wl >= 56);
    const bool lr = (wl == 55) || (wl == 63);

    __shared__ float ksm[PP][32];
    __shared__ float vsm[PP][32];
    __shared__ float ssm[PP][50];
    __shared__ float psm[169];

    const int tid = threadIdx.x;
    const float* qb = g_qkv + (size_t)win * PP * 768;

    for (int idx = tid; idx < PP * DH; idx += 64) {
        int tt = idx >> 5, d = idx & 31;
        ksm[tt][d] = qb[tt * 768 + 256 + head * 32 + d];
        vsm[tt][d] = qb[tt * 768 + 512 + head * 32 + d];
    }
    for (int idx = tid; idx < 169; idx += 64) psm[idx] = pos[idx];

    float4 q4[8];
    const int i = tid;
    if (i < PP) {
        const float4* qp = (const float4*)(qb + i * 768 + head * 32);
        #pragma unroll
        for (int d4 = 0; d4 < 8; d4++) q4[d4] = qp[d4];
    }
    __syncthreads();

    const float scale = 0.1767766952966369f;

    if (i < PP) {
        const int xi = i / Pw, yi = i - xi * Pw;
        int xj = 0, yj = 0;
        float mx = -1e30f;
        for (int j = 0; j < PP; j++) {
            const float4* krow = (const float4*)ksm[j];
            float s0 = 0.f, s1 = 0.f;
            #pragma unroll
            for (int d4 = 0; d4 < 8; d4 += 2) {
                float4 ka = krow[d4], kb = krow[d4 + 1];
                s0 = fmaf(q4[d4].x, ka.x, s0);   s0 = fmaf(q4[d4].y, ka.y, s0);
                s0 = fmaf(q4[d4].z, ka.z, s0);   s0 = fmaf(q4[d4].w, ka.w, s0);
                s1 = fmaf(q4[d4+1].x, kb.x, s1); s1 = fmaf(q4[d4+1].y, kb.y, s1);
                s1 = fmaf(q4[d4+1].z, kb.z, s1); s1 = fmaf(q4[d4+1].w, kb.w, s1);
            }
            float val = (s0 + s1) * scale + psm[(xj - xi + 6) * 13 + (yj - yi + 6)];
            if (ul && ((i >= 28) != (j >= 28))) val = -1e30f;
            if (lr && ((yi >= 4) != (yj >= 4))) val = -1e30f;
            ssm[i][j] = val;
            mx = fmaxf(mx, val);
            if (++yj == Pw) { yj = 0; xj++; }
        }
        float sum = 0.f;
        for (int j = 0; j < PP; j++) {
            float e = __expf(ssm[i][j] - mx);
            ssm[i][j] = e;
            sum += e;
        }
        float inv = 1.0f / sum;
        for (int j = 0; j < PP; j++) ssm[i][j] *= inv;
    }
    __syncthreads();

    float* aout = attn_out + (size_t)blk * PP * PP;
    for (int idx = tid; idx < PP * PP; idx += 64) {
        int r = idx / PP;
        aout[idx] = ssm[r][idx - r * PP];
    }

    if (i < PP) {
        float4 o4[8];
        #pragma unroll
        for (int d4 = 0; d4 < 8; d4++) o4[d4] = make_float4(0.f, 0.f, 0.f, 0.f);
        for (int j = 0; j < PP; j++) {
            float p = ssm[i][j];
            const float4* vrow = (const float4*)vsm[j];
            #pragma unroll
            for (int d4 = 0; d4 < 8; d4++) {
                float4 vv = vrow[d4];
                o4[d4].x = fmaf(p, vv.x, o4[d4].x);
                o4[d4].y = fmaf(p, vv.y, o4[d4].y);
                o4[d4].z = fmaf(p, vv.z, o4[d4].z);
                o4[d4].w = fmaf(p, vv.w, o4[d4].w);
            }
        }
        float4* ob = (float4*)(g_omid + ((size_t)win * PP + i) * INNER + head * 32);
        #pragma unroll
        for (int d4 = 0; d4 < 8; d4++)
            ob[d4] = make_float4(tf32r(o4[d4].x), tf32r(o4[d4].y),
                                 tf32r(o4[d4].z), tf32r(o4[d4].w));
    }
}

// ---------------------------------------------------------------------------
// Kernel 4: out GEMM, tf32 TC, 2-stage cp.async + bias + roll scatter.
// M=100352, N=128, K=256.
// ---------------------------------------------------------------------------
__global__ void out_gemm_tc(const float* __restrict__ b_out,
                            float* __restrict__ out)
{
    __shared__ float As[2][128][20];
    __shared__ float Bs[2][16][136];

    const int tid  = threadIdx.x;
    const int bm   = blockIdx.y * 128;
    const int lane = tid & 31, wid = tid >> 5;
    const int wm   = (wid & 1) * 64, wn = (wid >> 1) * 32;

    const int ar = tid & 127, ak = (tid >> 7) * 4;
    const float* agp = g_omid + (size_t)(bm + ar) * INNER + ak;
    const int bk = tid >> 4, bn8 = (tid & 15) * 8;
    const float* bgp = g_wout_t + (size_t)bk * 128 + bn8;

    unsigned int sA0 = (unsigned int)__cvta_generic_to_shared(&As[0][ar][ak]);
    unsigned int sA1 = (unsigned int)__cvta_generic_to_shared(&As[1][ar][ak]);
    unsigned int sB0 = (unsigned int)__cvta_generic_to_shared(&Bs[0][bk][bn8]);
    unsigned int sB1 = (unsigned int)__cvta_generic_to_shared(&Bs[1][bk][bn8]);

    float acc[4][4][4];
    #pragma unroll
    for (int i = 0; i < 4; i++)
        #pragma unroll
        for (int j = 0; j < 4; j++)
            #pragma unroll
            for (int c = 0; c < 4; c++) acc[i][j][c] = 0.f;

    cp16(sA0,      agp);
    cp16(sA0 + 32, agp + 8);
    cp16(sB0,      bgp);
    cp16(sB0 + 16, bgp + 4);
    cp_commit();

    #pragma unroll
    for (int ks = 0; ks < 16; ks++) {
        if (ks < 15) {
            const int k0 = (ks + 1) * 16;
            unsigned int dA = ((ks + 1) & 1) ? sA1 : sA0;
            unsigned int dB = ((ks + 1) & 1) ? sB1 : sB0;
            cp16(dA,      agp + k0);
            cp16(dA + 32, agp + k0 + 8);
            cp16(dB,      bgp + (size_t)k0 * 128);
            cp16(dB + 16, bgp + (size_t)k0 * 128 + 4);
            cp_commit();
            cp_wait1();
        } else {
            cp_wait0();
        }
        __syncthreads();
        const int st = ks & 1;
        #pragma unroll
        for (int k8 = 0; k8 < 16; k8 += 8) {
            unsigned int af[4][4], bf[4][2];
            const int kk = k8 + (lane & 3);
            #pragma unroll
            for (int mt = 0; mt < 4; mt++) {
                int r = wm + mt * 16 + (lane >> 2);
                af[mt][0] = __float_as_uint(As[st][r][kk]);
                af[mt][1] = __float_as_uint(As[st][r + 8][kk]);
                af[mt][2] = __float_as_uint(As[st][r][kk + 4]);
                af[mt][3] = __float_as_uint(As[st][r + 8][kk + 4]);
            }
            #pragma unroll
            for (int nt = 0; nt < 4; nt++) {
                int c = wn + nt * 8 + (lane >> 2);
                bf[nt][0] = __float_as_uint(Bs[st][kk][c]);
                bf[nt][1] = __float_as_uint(Bs[st][kk + 4][c]);
            }
            #pragma unroll
            for (int mt = 0; mt < 4; mt++)
                #pragma unroll
                for (int nt = 0; nt < 4; nt++)
                    mma_tf32(acc[mt][nt], af[mt][0], af[mt][1], af[mt][2], af[mt][3],
                             bf[nt][0], bf[nt][1]);
        }
        __syncthreads();
    }

    #pragma unroll
    for (int mt = 0; mt < 4; mt++) {
        #pragma unroll
        for (int half = 0; half < 2; half++) {
            int r = bm + wm + mt * 16 + (lane >> 2) + half * 8;
            int win = r / PP;
            int t   = r - win * PP;
            int b   = win >> 6;
            int wl  = win & 63;
            int i1  = wl >> 3, i2 = wl & 7;
            int xx  = t / Pw,  yy = t - (t / Pw) * Pw;
            int h = i1 * Pw + xx + 3; if (h >= HW) h -= HW;
            int w = i2 * Pw + yy + 3; if (w >= HW) w -= HW;
            size_t base = (size_t)b * Cc * HW * HW + (size_t)h * HW + w;
            #pragma unroll
            for (int nt = 0; nt < 4; nt++) {
                int c = wn + nt * 8 + (lane & 3) * 2;
                out[base + (size_t)c * (HW * HW)]       = acc[mt][nt][half * 2 + 0] + b_out[c];
                out[base + (size_t)(c + 1) * (HW * HW)] = acc[mt][nt][half * 2 + 1] + b_out[c + 1];
            }
        }
    }
}

// ---------------------------------------------------------------------------
extern "C" void kernel_launch(void* const* d_in, const int* in_sizes, int n_in,
                              void* d_out, int out_size)
{
    const float* x      = (const float*)d_in[0];
    const float* w_qkv  = (const float*)d_in[1];
    const float* w_out  = (const float*)d_in[2];
    const float* b_out  = (const float*)d_in[3];
    const float* pos    = (const float*)d_in[4];

    const long long O_ELEMS = (long long)Bb * Cc * HW * HW;
    const long long A_ELEMS = (long long)WINS * HEADS * PP * PP;

    float* outp = (float*)d_out;
    float* o_ptr;
    float* attn_ptr;

    if ((long long)out_size >= O_ELEMS + A_ELEMS) {
        o_ptr    = outp;
        attn_ptr = outp + O_ELEMS;
    } else if ((long long)out_size == A_ELEMS) {
        attn_ptr = outp;
        cudaGetSymbolAddress((void**)&o_ptr, g_o_dump);
    } else {
        o_ptr = outp;
        cudaGetSymbolAddress((void**)&attn_ptr, g_attn_dump);
    }

    transpose_w<<<512, 256>>>(w_qkv, w_out);
    gather_x<<<Bb * 49, 256>>>(x);
    qkv_gemm_tc<<<dim3(768 / 128, MROWS / 128), 256>>>();
    attn_kernel<<<WINS * HEADS, 64>>>(pos, attn_ptr);
    out_gemm_tc<<<dim3(1, MROWS / 128), 256>>>(b_out, o_ptr);
}

// round 6
// speedup vs baseline: 2.3906x; 1.1094x over previous
#include <cuda_runtime.h>
#include <stdint.h>
#include <math.h>

#define Pw    7
#define PP    49
#define HEADS 8
#define DH    32
#define INNER 256
#define Cc    128
#define Bb    32
#define HW    56
#define WINS  2048
#define MROWS (WINS*PP)    // 100352

static __device__ float g_xw  [(size_t)MROWS * Cc];
static __device__ float g_qkv [(size_t)MROWS * 3 * INNER];
static __device__ float g_omid[(size_t)MROWS * INNER];
static __device__ float g_wqkv_t[768 * 128];
static __device__ float g_wout_t[256 * 128];
static __device__ float g_attn_dump[(size_t)WINS * HEADS * PP * PP];
static __device__ float g_o_dump  [(size_t)Bb * Cc * HW * HW];

__device__ __forceinline__ unsigned int f2tf32(float f) {
    unsigned int u; asm("cvt.rna.tf32.f32 %0, %1;" : "=r"(u) : "f"(f)); return u;
}
__device__ __forceinline__ float tf32r(float f) { return __uint_as_float(f2tf32(f)); }

__device__ __forceinline__ void mma_tf32(float c[4],
    unsigned int a0, unsigned int a1, unsigned int a2, unsigned int a3,
    unsigned int b0, unsigned int b1)
{
    asm volatile(
        "mma.sync.aligned.m16n8k8.row.col.f32.tf32.tf32.f32 "
        "{%0,%1,%2,%3}, {%4,%5,%6,%7}, {%8,%9}, {%0,%1,%2,%3};"
        : "+f"(c[0]), "+f"(c[1]), "+f"(c[2]), "+f"(c[3])
        : "r"(a0), "r"(a1), "r"(a2), "r"(a3), "r"(b0), "r"(b1));
}

__device__ __forceinline__ void cp16(unsigned int saddr, const void* gaddr) {
    asm volatile("cp.async.cg.shared.global [%0], [%1], 16;" :: "r"(saddr), "l"(gaddr));
}
__device__ __forceinline__ void cp_commit() { asm volatile("cp.async.commit_group;"); }
__device__ __forceinline__ void cp_wait1()  { asm volatile("cp.async.wait_group 1;"); }
__device__ __forceinline__ void cp_wait0()  { asm volatile("cp.async.wait_group 0;"); }

// ---------------------------------------------------------------------------
// Kernel 0: transpose + tf32-round weights (tiny)
// ---------------------------------------------------------------------------
__global__ void transpose_w(const float* __restrict__ wq, const float* __restrict__ wo)
{
    int idx = blockIdx.x * 256 + threadIdx.x;
    if (idx < 768 * 128) {
        int k = idx / 768, n = idx - k * 768;
        g_wqkv_t[idx] = tf32r(wq[n * 128 + k]);
    }
    int i2 = idx - 768 * 128;
    if (i2 >= 0 && i2 < 256 * 128) {
        int k = i2 / 128, n = i2 - k * 128;
        g_wout_t[i2] = tf32r(wo[n * 256 + k]);
    }
}

// ---------------------------------------------------------------------------
// Kernel 1: gather (roll -3,-3 + window partition) -> g_xw, tf32-rounded.
// ---------------------------------------------------------------------------
__global__ void gather_x(const float* __restrict__ x)
{
    __shared__ float sm[128][65];
    const int b  = blockIdx.x / 49;
    const int p0 = (blockIdx.x - b * 49) * 64;
    const int tid = threadIdx.x;

    for (int i = tid; i < 128 * 64; i += 256) {
        int c = i >> 6, p = i & 63;
        sm[c][p] = x[((size_t)b * 128 + c) * 3136 + p0 + p];
    }
    __syncthreads();
    for (int i = tid; i < 64 * 128; i += 256) {
        int p = i >> 7, c = i & 127;
        int pix = p0 + p;
        int h = pix / HW, w = pix - h * HW;
        int hs = h - 3; if (hs < 0) hs += HW;
        int ws = w - 3; if (ws < 0) ws += HW;
        int win = b * 64 + (hs / Pw) * 8 + (ws / Pw);
        int t   = (hs % Pw) * Pw + (ws % Pw);
        g_xw[((size_t)win * PP + t) * Cc + c] = tf32r(sm[c][p]);
    }
}

// ---------------------------------------------------------------------------
// Kernel 2: QKV GEMM, tf32 TC, 2-stage cp.async (unchanged from R4)
// ---------------------------------------------------------------------------
__global__ void qkv_gemm_tc()
{
    __shared__ float As[2][128][20];
    __shared__ float Bs[2][16][136];

    const int tid  = threadIdx.x;
    const int bm   = blockIdx.y * 128;
    const int bn   = blockIdx.x * 128;
    const int lane = tid & 31, wid = tid >> 5;
    const int wm   = (wid & 1) * 64, wn = (wid >> 1) * 32;

    const int ar = tid & 127, ak = (tid >> 7) * 4;
    const float* agp = g_xw + (size_t)(bm + ar) * Cc + ak;
    const int bk = tid >> 4, bn8 = (tid & 15) * 8;
    const float* bgp = g_wqkv_t + (size_t)bk * 768 + bn + bn8;

    unsigned int sA0 = (unsigned int)__cvta_generic_to_shared(&As[0][ar][ak]);
    unsigned int sA1 = (unsigned int)__cvta_generic_to_shared(&As[1][ar][ak]);
    unsigned int sB0 = (unsigned int)__cvta_generic_to_shared(&Bs[0][bk][bn8]);
    unsigned int sB1 = (unsigned int)__cvta_generic_to_shared(&Bs[1][bk][bn8]);

    float acc[4][4][4];
    #pragma unroll
    for (int i = 0; i < 4; i++)
        #pragma unroll
        for (int j = 0; j < 4; j++)
            #pragma unroll
            for (int c = 0; c < 4; c++) acc[i][j][c] = 0.f;

    cp16(sA0,      agp);
    cp16(sA0 + 32, agp + 8);
    cp16(sB0,      bgp);
    cp16(sB0 + 16, bgp + 4);
    cp_commit();

    #pragma unroll
    for (int ks = 0; ks < 8; ks++) {
        if (ks < 7) {
            const int k0 = (ks + 1) * 16;
            unsigned int dA = ((ks + 1) & 1) ? sA1 : sA0;
            unsigned int dB = ((ks + 1) & 1) ? sB1 : sB0;
            cp16(dA,      agp + k0);
            cp16(dA + 32, agp + k0 + 8);
            cp16(dB,      bgp + (size_t)k0 * 768);
            cp16(dB + 16, bgp + (size_t)k0 * 768 + 4);
            cp_commit();
            cp_wait1();
        } else {
            cp_wait0();
        }
        __syncthreads();
        const int st = ks & 1;
        #pragma unroll
        for (int k8 = 0; k8 < 16; k8 += 8) {
            unsigned int af[4][4], bf[4][2];
            const int kk = k8 + (lane & 3);
            #pragma unroll
            for (int mt = 0; mt < 4; mt++) {
                int r = wm + mt * 16 + (lane >> 2);
                af[mt][0] = __float_as_uint(As[st][r][kk]);
                af[mt][1] = __float_as_uint(As[st][r + 8][kk]);
                af[mt][2] = __float_as_uint(As[st][r][kk + 4]);
                af[mt][3] = __float_as_uint(As[st][r + 8][kk + 4]);
            }
            #pragma unroll
            for (int nt = 0; nt < 4; nt++) {
                int c = wn + nt * 8 + (lane >> 2);
                bf[nt][0] = __float_as_uint(Bs[st][kk][c]);
                bf[nt][1] = __float_as_uint(Bs[st][kk + 4][c]);
            }
            #pragma unroll
            for (int mt = 0; mt < 4; mt++)
                #pragma unroll
                for (int nt = 0; nt < 4; nt++)
                    mma_tf32(acc[mt][nt], af[mt][0], af[mt][1], af[mt][2], af[mt][3],
                             bf[nt][0], bf[nt][1]);
        }
        __syncthreads();
    }

    #pragma unroll
    for (int mt = 0; mt < 4; mt++) {
        int r0 = bm + wm + mt * 16 + (lane >> 2);
        #pragma unroll
        for (int nt = 0; nt < 4; nt++) {
            int c = bn + wn + nt * 8 + (lane & 3) * 2;
            *(float2*)&g_qkv[(size_t)r0 * 768 + c] =
                make_float2(acc[mt][nt][0], acc[mt][nt][1]);
            *(float2*)&g_qkv[(size_t)(r0 + 8) * 768 + c] =
                make_float2(acc[mt][nt][2], acc[mt][nt][3]);
        }
    }
}

// ---------------------------------------------------------------------------
// Kernel 3: tensor-core attention. Block = (win, head), 64 threads (2 warps).
// Warp w owns m-tiles {2w, 2w+1} (rows 32w..32w+31) of the padded 64x56 S.
// ---------------------------------------------------------------------------
__global__ void __launch_bounds__(64) attn_tc_kernel(const float* __restrict__ pos,
                                                     float* __restrict__ attn_out)
{
    const int blk  = blockIdx.x;
    const int win  = blk >> 3;
    const int head = blk & 7;
    const int wl   = win & 63;
    const bool ul = (wl >= 56);
    const bool lr = (wl == 55) || (wl == 63);

    __shared__ float qsm [64][36];   // stride 36 ≡ 4 (mod 32): A-frag conflict-free
    __shared__ float ktsm[32][72];   // K^T [d][j], stride 72 ≡ 8: B-frag conflict-free
    __shared__ float vsm [56][40];   // V [j][d], stride 40 ≡ 8
    __shared__ float ssm [64][68];   // P (fp32), stride 68 ≡ 4
    __shared__ float psm [169];

    const int tid  = threadIdx.x;
    const int lane = tid & 31;
    const int warp = tid >> 5;
    const int wm   = warp * 32;
    const int qr   = lane >> 2;      // quad row
    const int ql   = lane & 3;       // quad lane

    const float* qb = g_qkv + (size_t)win * PP * 768 + head * 32;

    // zero pads (q rows 49..63, v rows 49..55)
    for (int idx = tid; idx < 15 * 36; idx += 64) qsm[49 + idx / 36][idx % 36] = 0.f;
    for (int idx = tid; idx < 7 * 40;  idx += 64) vsm[49 + idx / 40][idx % 40] = 0.f;
    for (int idx = tid; idx < 169;     idx += 64) psm[idx] = pos[idx];

    // load q/k/v (gmem coalesced in 128B chunks); tf32-round q,k,v
    for (int idx = tid; idx < PP * 32; idx += 64) {
        int j = idx >> 5, d = idx & 31;
        qsm[j][d]  = tf32r(qb[j * 768 + d]);
        ktsm[d][j] = tf32r(qb[j * 768 + 256 + d]);
        vsm[j][d]  = tf32r(qb[j * 768 + 512 + d]);
    }
    __syncthreads();

    // ---- S = Q @ K^T  (per warp: 2 m-tiles x 7 n-tiles x 4 k-steps) ----
    float s[2][7][4];
    #pragma unroll
    for (int mt = 0; mt < 2; mt++)
        #pragma unroll
        for (int nt = 0; nt < 7; nt++)
            #pragma unroll
            for (int c = 0; c < 4; c++) s[mt][nt][c] = 0.f;

    #pragma unroll
    for (int ks = 0; ks < 4; ks++) {
        const int kk = ks * 8 + ql;
        unsigned int a[2][4], b[7][2];
        #pragma unroll
        for (int mt = 0; mt < 2; mt++) {
            int r = wm + mt * 16 + qr;
            a[mt][0] = __float_as_uint(qsm[r][kk]);
            a[mt][1] = __float_as_uint(qsm[r + 8][kk]);
            a[mt][2] = __float_as_uint(qsm[r][kk + 4]);
            a[mt][3] = __float_as_uint(qsm[r + 8][kk + 4]);
        }
        #pragma unroll
        for (int nt = 0; nt < 7; nt++) {
            int c = nt * 8 + qr;
            b[nt][0] = __float_as_uint(ktsm[kk][c]);
            b[nt][1] = __float_as_uint(ktsm[kk + 4][c]);
        }
        #pragma unroll
        for (int mt = 0; mt < 2; mt++)
            #pragma unroll
            for (int nt = 0; nt < 7; nt++)
                mma_tf32(s[mt][nt], a[mt][0], a[mt][1], a[mt][2], a[mt][3],
                         b[nt][0], b[nt][1]);
    }

    // ---- bias + masks + softmax in fragments ----
    const float scale = 0.1767766952966369f;
    #pragma unroll
    for (int mt = 0; mt < 2; mt++) {
        const int rA = wm + mt * 16 + qr;
        const int rB = rA + 8;
        const int iA = (rA < PP) ? rA : 48;
        const int iB = (rB < PP) ? rB : 48;
        const int xiA = iA / Pw, yiA = iA - xiA * Pw;
        const int xiB = iB / Pw, yiB = iB - xiB * Pw;

        // bias + mask
        #pragma unroll
        for (int nt = 0; nt < 7; nt++) {
            #pragma unroll
            for (int e = 0; e < 4; e++) {
                int j  = nt * 8 + ql * 2 + (e & 1);
                int xi = (e < 2) ? xiA : xiB;
                int yi = (e < 2) ? yiA : yiB;
                int r  = (e < 2) ? rA : rB;
                int jc = (j < PP) ? j : 48;
                int xj = jc / Pw, yj = jc - xj * Pw;
                float val = s[mt][nt][e] * scale + psm[(xj - xi + 6) * 13 + (yj - yi + 6)];
                if (j >= PP) val = -1e30f;
                if (ul && ((r >= 28) != (j >= 28))) val = -1e30f;
                if (lr && ((yi >= 4) != (yj >= 4))) val = -1e30f;
                s[mt][nt][e] = val;
            }
        }
        // row max (rows rA: e0,e1; rB: e2,e3), reduce over quad
        float mA = -1e30f, mB = -1e30f;
        #pragma unroll
        for (int nt = 0; nt < 7; nt++) {
            mA = fmaxf(mA, fmaxf(s[mt][nt][0], s[mt][nt][1]));
            mB = fmaxf(mB, fmaxf(s[mt][nt][2], s[mt][nt][3]));
        }
        mA = fmaxf(mA, __shfl_xor_sync(0xffffffffu, mA, 1));
        mA = fmaxf(mA, __shfl_xor_sync(0xffffffffu, mA, 2));
        mB = fmaxf(mB, __shfl_xor_sync(0xffffffffu, mB, 1));
        mB = fmaxf(mB, __shfl_xor_sync(0xffffffffu, mB, 2));

        float sA = 0.f, sB = 0.f;
        #pragma unroll
        for (int nt = 0; nt < 7; nt++) {
            s[mt][nt][0] = __expf(s[mt][nt][0] - mA);
            s[mt][nt][1] = __expf(s[mt][nt][1] - mA);
            s[mt][nt][2] = __expf(s[mt][nt][2] - mB);
            s[mt][nt][3] = __expf(s[mt][nt][3] - mB);
            sA += s[mt][nt][0] + s[mt][nt][1];
            sB += s[mt][nt][2] + s[mt][nt][3];
        }
        sA += __shfl_xor_sync(0xffffffffu, sA, 1);
        sA += __shfl_xor_sync(0xffffffffu, sA, 2);
        sB += __shfl_xor_sync(0xffffffffu, sB, 1);
        sB += __shfl_xor_sync(0xffffffffu, sB, 2);
        const float iAu = 1.0f / sA, iBu = 1.0f / sB;

        #pragma unroll
        for (int nt = 0; nt < 7; nt++) {
            int j0 = nt * 8 + ql * 2;
            float p0 = s[mt][nt][0] * iAu, p1 = s[mt][nt][1] * iAu;
            float p2 = s[mt][nt][2] * iBu, p3 = s[mt][nt][3] * iBu;
            *(float2*)&ssm[rA][j0] = make_float2(p0, p1);
            *(float2*)&ssm[rB][j0] = make_float2(p2, p3);
        }
    }
    __syncthreads();

    // coalesced attn write (fp32, full precision)
    float* aout = attn_out + (size_t)blk * PP * PP;
    for (int idx = tid; idx < PP * PP; idx += 64) {
        int r = idx / PP;
        aout[idx] = ssm[r][idx - r * PP];
    }

    // ---- O = P @ V  (per warp: 2 m-tiles x 4 n-tiles x 7 k-steps) ----
    float o[2][4][4];
    #pragma unroll
    for (int mt = 0; mt < 2; mt++)
        #pragma unroll
        for (int nt = 0; nt < 4; nt++)
            #pragma unroll
            for (int c = 0; c < 4; c++) o[mt][nt][c] = 0.f;

    #pragma unroll
    for (int ks = 0; ks < 7; ks++) {
        const int kk = ks * 8 + ql;
        unsigned int a[2][4], b[4][2];
        #pragma unroll
        for (int mt = 0; mt < 2; mt++) {
            int r = wm + mt * 16 + qr;
            a[mt][0] = f2tf32(ssm[r][kk]);
            a[mt][1] = f2tf32(ssm[r + 8][kk]);
            a[mt][2] = f2tf32(ssm[r][kk + 4]);
            a[mt][3] = f2tf32(ssm[r + 8][kk + 4]);
        }
        #pragma unroll
        for (int nt = 0; nt < 4; nt++) {
            int c = nt * 8 + qr;
            b[nt][0] = __float_as_uint(vsm[kk][c]);
            b[nt][1] = __float_as_uint(vsm[kk + 4][c]);
        }
        #pragma unroll
        for (int mt = 0; mt < 2; mt++)
            #pragma unroll
            for (int nt = 0; nt < 4; nt++)
                mma_tf32(o[mt][nt], a[mt][0], a[mt][1], a[mt][2], a[mt][3],
                         b[nt][0], b[nt][1]);
    }

    // store O (tf32-rounded for the next tf32 GEMM)
    float* ob = g_omid + (size_t)win * PP * INNER + head * 32;
    #pragma unroll
    for (int mt = 0; mt < 2; mt++) {
        int rA = wm + mt * 16 + qr, rB = rA + 8;
        #pragma unroll
        for (int nt = 0; nt < 4; nt++) {
            int c = nt * 8 + ql * 2;
            if (rA < PP)
                *(float2*)&ob[(size_t)rA * INNER + c] =
                    make_float2(tf32r(o[mt][nt][0]), tf32r(o[mt][nt][1]));
            if (rB < PP)
                *(float2*)&ob[(size_t)rB * INNER + c] =
                    make_float2(tf32r(o[mt][nt][2]), tf32r(o[mt][nt][3]));
        }
    }
}

// ---------------------------------------------------------------------------
// Kernel 4: out GEMM, tf32 TC, 2-stage cp.async + bias + roll scatter.
// ---------------------------------------------------------------------------
__global__ void out_gemm_tc(const float* __restrict__ b_out,
                            float* __restrict__ out)
{
    __shared__ float As[2][128][20];
    __shared__ float Bs[2][16][136];

    const int tid  = threadIdx.x;
    const int bm   = blockIdx.y * 128;
    const int lane = tid & 31, wid = tid >> 5;
    const int wm   = (wid & 1) * 64, wn = (wid >> 1) * 32;

    const int ar = tid & 127, ak = (tid >> 7) * 4;
    const float* agp = g_omid + (size_t)(bm + ar) * INNER + ak;
    const int bk = tid >> 4, bn8 = (tid & 15) * 8;
    const float* bgp = g_wout_t + (size_t)bk * 128 + bn8;

    unsigned int sA0 = (unsigned int)__cvta_generic_to_shared(&As[0][ar][ak]);
    unsigned int sA1 = (unsigned int)__cvta_generic_to_shared(&As[1][ar][ak]);
    unsigned int sB0 = (unsigned int)__cvta_generic_to_shared(&Bs[0][bk][bn8]);
    unsigned int sB1 = (unsigned int)__cvta_generic_to_shared(&Bs[1][bk][bn8]);

    float acc[4][4][4];
    #pragma unroll
    for (int i = 0; i < 4; i++)
        #pragma unroll
        for (int j = 0; j < 4; j++)
            #pragma unroll
            for (int c = 0; c < 4; c++) acc[i][j][c] = 0.f;

    cp16(sA0,      agp);
    cp16(sA0 + 32, agp + 8);
    cp16(sB0,      bgp);
    cp16(sB0 + 16, bgp + 4);
    cp_commit();

    #pragma unroll
    for (int ks = 0; ks < 16; ks++) {
        if (ks < 15) {
            const int k0 = (ks + 1) * 16;
            unsigned int dA = ((ks + 1) & 1) ? sA1 : sA0;
            unsigned int dB = ((ks + 1) & 1) ? sB1 : sB0;
            cp16(dA,      agp + k0);
            cp16(dA + 32, agp + k0 + 8);
            cp16(dB,      bgp + (size_t)k0 * 128);
            cp16(dB + 16, bgp + (size_t)k0 * 128 + 4);
            cp_commit();
            cp_wait1();
        } else {
            cp_wait0();
        }
        __syncthreads();
        const int st = ks & 1;
        #pragma unroll
        for (int k8 = 0; k8 < 16; k8 += 8) {
            unsigned int af[4][4], bf[4][2];
            const int kk = k8 + (lane & 3);
            #pragma unroll
            for (int mt = 0; mt < 4; mt++) {
                int r = wm + mt * 16 + (lane >> 2);
                af[mt][0] = __float_as_uint(As[st][r][kk]);
                af[mt][1] = __float_as_uint(As[st][r + 8][kk]);
                af[mt][2] = __float_as_uint(As[st][r][kk + 4]);
                af[mt][3] = __float_as_uint(As[st][r + 8][kk + 4]);
            }
            #pragma unroll
            for (int nt = 0; nt < 4; nt++) {
                int c = wn + nt * 8 + (lane >> 2);
                bf[nt][0] = __float_as_uint(Bs[st][kk][c]);
                bf[nt][1] = __float_as_uint(Bs[st][kk + 4][c]);
            }
            #pragma unroll
            for (int mt = 0; mt < 4; mt++)
                #pragma unroll
                for (int nt = 0; nt < 4; nt++)
                    mma_tf32(acc[mt][nt], af[mt][0], af[mt][1], af[mt][2], af[mt][3],
                             bf[nt][0], bf[nt][1]);
        }
        __syncthreads();
    }

    #pragma unroll
    for (int mt = 0; mt < 4; mt++) {
        #pragma unroll
        for (int half = 0; half < 2; half++) {
            int r = bm + wm + mt * 16 + (lane >> 2) + half * 8;
            int win = r / PP;
            int t   = r - win * PP;
            int b   = win >> 6;
            int wl  = win & 63;
            int i1  = wl >> 3, i2 = wl & 7;
            int xx  = t / Pw,  yy = t - (t / Pw) * Pw;
            int h = i1 * Pw + xx + 3; if (h >= HW) h -= HW;
            int w = i2 * Pw + yy + 3; if (w >= HW) w -= HW;
            size_t base = (size_t)b * Cc * HW * HW + (size_t)h * HW + w;
            #pragma unroll
            for (int nt = 0; nt < 4; nt++) {
                int c = wn + nt * 8 + (lane & 3) * 2;
                out[base + (size_t)c * (HW * HW)]       = acc[mt][nt][half * 2 + 0] + b_out[c];
                out[base + (size_t)(c + 1) * (HW * HW)] = acc[mt][nt][half * 2 + 1] + b_out[c + 1];
            }
        }
    }
}

// ---------------------------------------------------------------------------
extern "C" void kernel_launch(void* const* d_in, const int* in_sizes, int n_in,
                              void* d_out, int out_size)
{
    const float* x      = (const float*)d_in[0];
    const float* w_qkv  = (const float*)d_in[1];
    const float* w_out  = (const float*)d_in[2];
    const float* b_out  = (const float*)d_in[3];
    const float* pos    = (const float*)d_in[4];

    const long long O_ELEMS = (long long)Bb * Cc * HW * HW;
    const long long A_ELEMS = (long long)WINS * HEADS * PP * PP;

    float* outp = (float*)d_out;
    float* o_ptr;
    float* attn_ptr;

    if ((long long)out_size >= O_ELEMS + A_ELEMS) {
        o_ptr    = outp;
        attn_ptr = outp + O_ELEMS;
    } else if ((long long)out_size == A_ELEMS) {
        attn_ptr = outp;
        cudaGetSymbolAddress((void**)&o_ptr, g_o_dump);
    } else {
        o_ptr = outp;
        cudaGetSymbolAddress((void**)&attn_ptr, g_attn_dump);
    }

    transpose_w<<<512, 256>>>(w_qkv, w_out);
    gather_x<<<Bb * 49, 256>>>(x);
    qkv_gemm_tc<<<dim3(768 / 128, MROWS / 128), 256>>>();
    attn_tc_kernel<<<WINS * HEADS, 64>>>(pos, attn_ptr);
    out_gemm_tc<<<dim3(1, MROWS / 128), 256>>>(b_out, o_ptr);
}